// round 2
// baseline (speedup 1.0000x reference)
#include <cuda_runtime.h>

#define SLOPE 0.2f
#define NROW  328
#define MAXN  100352
#define MAXE  1000192
#define MAXNB (MAXE / 64)

__device__ float g_node[(size_t)MAXN * NROW];
__device__ float g_zbuf[(size_t)MAXE * 64];
__device__ float g_partM[64 * MAXNB];
__device__ float g_partS[64 * MAXNB];
__device__ float g_W2[64 * 128];
__device__ float g_Wn[64 * NROW];
__device__ float g_Wa3[64];
__device__ float g_bwe[64];
__device__ float g_cvec[64];
__device__ float g_Mg[64];
__device__ float g_invS[64];
__device__ float g_battn;
__device__ int   g_idx64;

__device__ __forceinline__ float lrelu_f(float x) { return x >= 0.f ? x : SLOPE * x; }

__global__ void k_prep(const float* __restrict__ W_attn, const float* __restrict__ b_attn,
                       const float* __restrict__ W_upd,  const float* __restrict__ b_upd,
                       const float* __restrict__ W_edge, const float* __restrict__ b_edge,
                       const float* __restrict__ W_node, const float* __restrict__ b_node,
                       const unsigned* __restrict__ eidx_raw)
{
    int t = threadIdx.x;
    for (int idx = t; idx < 64 * 128; idx += 256) {
        int k = idx >> 7, c = idx & 127;
        float v;
        if (c < 64) v = W_upd[(128 + k) * 64 + c];
        else { int cc = c - 64; float s = 0.f;
               for (int j = 0; j < 64; j++) s += W_upd[(128 + k) * 64 + j] * W_edge[j * 64 + cc];
               v = s; }
        g_W2[idx] = v;
    }
    for (int idx = t; idx < 64 * NROW; idx += 256) {
        int k = idx / NROW, c = idx % NROW;
        float v = 0.f;
        if (c < 64)        v = W_upd[k * 64 + c];
        else if (c < 128)  v = W_upd[(64 + k) * 64 + (c - 64)];
        else if (c < 192)  v = W_node[k * 64 + (c - 128)];
        else if (c < 256) { int cc = c - 192; float s = 0.f;
                            for (int j = 0; j < 64; j++) s += W_upd[k * 64 + j] * W_edge[j * 64 + cc];
                            v = s; }
        else if (c < 320) { int cc = c - 256; float s = 0.f;
                            for (int j = 0; j < 64; j++) s += W_upd[(64 + k) * 64 + j] * W_edge[j * 64 + cc];
                            v = s; }
        else if (c == 320) v = W_attn[k];
        else if (c == 321) v = W_attn[64 + k];
        g_Wn[idx] = v;
    }
    if (t < 64) {
        float s = 0.f;
        for (int j = 0; j < 64; j++) s += b_upd[j] * W_edge[j * 64 + t];
        g_bwe[t]  = s;
        g_cvec[t] = b_edge[t] + 2.f * b_node[t];
        g_Wa3[t]  = W_attn[128 + t];
    }
    if (t == 0) {
        g_battn = b_attn[0];
        int is64 = 1;
        for (int i = 0; i < 32; i++)
            if (eidx_raw[2 * i + 1] != 0u) { is64 = 0; break; }
        g_idx64 = is64;
    }
}

__global__ __launch_bounds__(256) void k_node(const float* __restrict__ ne, int N)
{
    __shared__ float sX[32 * 64];
    __shared__ float sW[16 * NROW];
    int t = threadIdx.x;
    int n0 = blockIdx.x * 32;

    for (int i = t; i < 32 * 64; i += 256) {
        int n = n0 + (i >> 6);
        sX[i] = (n < N) ? ne[(size_t)n * 64 + (i & 63)] : 0.f;
    }
    int w = t >> 5, lane = t & 31;
    bool p2 = (lane * 4) < (NROW - 256);

    float acc[4][12];
    #pragma unroll
    for (int i = 0; i < 4; i++)
        #pragma unroll
        for (int j = 0; j < 12; j++) acc[i][j] = 0.f;

    for (int stage = 0; stage < 4; stage++) {
        __syncthreads();
        for (int i = t; i < 16 * NROW; i += 256) sW[i] = g_Wn[stage * 16 * NROW + i];
        __syncthreads();
        #pragma unroll 4
        for (int kk = 0; kk < 16; kk++) {
            int k = stage * 16 + kk;
            float4 w0 = *(float4*)&sW[kk * NROW + lane * 4];
            float4 w1 = *(float4*)&sW[kk * NROW + 128 + lane * 4];
            float4 w2 = p2 ? *(float4*)&sW[kk * NROW + 256 + lane * 4]
                           : make_float4(0.f, 0.f, 0.f, 0.f);
            #pragma unroll
            for (int i = 0; i < 4; i++) {
                float x = sX[(w * 4 + i) * 64 + k];
                acc[i][0] += x * w0.x; acc[i][1] += x * w0.y; acc[i][2]  += x * w0.z; acc[i][3]  += x * w0.w;
                acc[i][4] += x * w1.x; acc[i][5] += x * w1.y; acc[i][6]  += x * w1.z; acc[i][7]  += x * w1.w;
                acc[i][8] += x * w2.x; acc[i][9] += x * w2.y; acc[i][10] += x * w2.z; acc[i][11] += x * w2.w;
            }
        }
    }
    #pragma unroll
    for (int i = 0; i < 4; i++) {
        int n = n0 + w * 4 + i;
        if (n >= N) continue;
        float* dst = g_node + (size_t)n * NROW;
        *(float4*)&dst[lane * 4]       = make_float4(acc[i][0], acc[i][1], acc[i][2],  acc[i][3]);
        *(float4*)&dst[128 + lane * 4] = make_float4(acc[i][4], acc[i][5], acc[i][6],  acc[i][7]);
        if (p2)
            *(float4*)&dst[256 + lane * 4] = make_float4(acc[i][8], acc[i][9], acc[i][10], acc[i][11]);
    }
}

__global__ __launch_bounds__(256) void k_edge(const float* __restrict__ eemb,
                                              const void*  __restrict__ eidx,
                                              const float* __restrict__ bupd,
                                              float*       __restrict__ out,
                                              int E)
{
    __shared__ float sA[64 * 65];
    __shared__ float sW[32 * 128];
    __shared__ float sWa[64];
    __shared__ float sGate[64];
    __shared__ int   sSrc[64], sDst[64];

    int t = threadIdx.x;
    int e0g = blockIdx.x * 64;
    int idx64 = g_idx64;

    if (t < 128) {
        int j = t & 63;
        int ee = min(e0g + j, E - 1);
        size_t pos = (t < 64) ? (size_t)ee : (size_t)E + (size_t)ee;
        int v = idx64 ? (int)((const long long*)eidx)[pos] : ((const int*)eidx)[pos];
        if (t < 64) sSrc[j] = v; else sDst[j] = v;
    }
    if (t >= 128 && t < 192) sWa[t - 128] = g_Wa3[t - 128];
    for (int i = t; i < 64 * 64; i += 256) {
        int e = i >> 6, k = i & 63;
        int ee = min(e0g + e, E - 1);
        sA[e * 65 + k] = eemb[(size_t)ee * 64 + k];
    }
    __syncthreads();

    int cg = t >> 4, eg = t & 15;
    int c0 = cg * 4;
    int eb = eg * 4;

    float acc[4][8];
    #pragma unroll
    for (int i = 0; i < 4; i++)
        #pragma unroll
        for (int j = 0; j < 8; j++) acc[i][j] = 0.f;

    for (int stage = 0; stage < 2; stage++) {
        for (int i = t; i < 32 * 128; i += 256) sW[i] = g_W2[stage * 4096 + i];
        __syncthreads();
        #pragma unroll 8
        for (int kk = 0; kk < 32; kk++) {
            float4 b0 = *(float4*)&sW[kk * 128 + c0];
            float4 b1 = *(float4*)&sW[kk * 128 + 64 + c0];
            int k = stage * 32 + kk;
            #pragma unroll
            for (int i = 0; i < 4; i++) {
                float a = sA[(eb + i) * 65 + k];
                acc[i][0] += a * b0.x; acc[i][1] += a * b0.y; acc[i][2] += a * b0.z; acc[i][3] += a * b0.w;
                acc[i][4] += a * b1.x; acc[i][5] += a * b1.y; acc[i][6] += a * b1.z; acc[i][7] += a * b1.w;
            }
        }
        __syncthreads();
    }

    if (t < 64) {
        float s = 0.f;
        #pragma unroll 16
        for (int k = 0; k < 64; k++) s += sA[t * 65 + k] * sWa[k];
        int src = sSrc[t], dst = sDst[t];
        float a1 = g_node[(size_t)src * NROW + 320];
        float a2 = g_node[(size_t)dst * NROW + 321];
        float pre = a1 + a2 + s + g_battn;
        sGate[t] = 1.f / (1.f + __expf(-lrelu_f(pre)));
    }
    __syncthreads();

    float4 buv = *(const float4*)&bupd[c0];
    float4 bwv = *(const float4*)&g_bwe[c0];
    float4 cvv = *(const float4*)&g_cvec[c0];

    float zs[4][4];
    bool  val[4];
    #pragma unroll
    for (int i = 0; i < 4; i++) {
        int e = eb + i;
        val[i] = (e0g + e) < E;
        int src = sSrc[e], dst = sDst[e];
        const float* ns = g_node + (size_t)src * NROW;
        const float* nd = g_node + (size_t)dst * NROW;
        float gt = sGate[e];
        float4 p1  = *(const float4*)(ns + c0);
        float4 p2  = *(const float4*)(nd + 64 + c0);
        float4 p3s = *(const float4*)(ns + 128 + c0);
        float4 p3d = *(const float4*)(nd + 128 + c0);
        float4 q1  = *(const float4*)(ns + 192 + c0);
        float4 q2  = *(const float4*)(nd + 256 + c0);

        float4 up, zz;
        up.x = gt * (p1.x + p2.x + acc[i][0] + buv.x);
        up.y = gt * (p1.y + p2.y + acc[i][1] + buv.y);
        up.z = gt * (p1.z + p2.z + acc[i][2] + buv.z);
        up.w = gt * (p1.w + p2.w + acc[i][3] + buv.w);

        float pr;
        pr = gt * (q1.x + q2.x + acc[i][4] + bwv.x) + p3s.x + p3d.x + cvv.x; zz.x = lrelu_f(pr);
        pr = gt * (q1.y + q2.y + acc[i][5] + bwv.y) + p3s.y + p3d.y + cvv.y; zz.y = lrelu_f(pr);
        pr = gt * (q1.z + q2.z + acc[i][6] + bwv.z) + p3s.z + p3d.z + cvv.z; zz.z = lrelu_f(pr);
        pr = gt * (q1.w + q2.w + acc[i][7] + bwv.w) + p3s.w + p3d.w + cvv.w; zz.w = lrelu_f(pr);

        if (val[i]) {
            size_t off = (size_t)(e0g + e) * 64 + c0;
            *(float4*)&out[off]    = up;
            *(float4*)&g_zbuf[off] = zz;
        }
        zs[i][0] = zz.x; zs[i][1] = zz.y; zs[i][2] = zz.z; zs[i][3] = zz.w;
    }

    float m[4], sv[4];
    #pragma unroll
    for (int j = 0; j < 4; j++) {
        float mm = -1e30f;
        #pragma unroll
        for (int i = 0; i < 4; i++) if (val[i]) mm = fmaxf(mm, zs[i][j]);
        float ss = 0.f;
        #pragma unroll
        for (int i = 0; i < 4; i++) if (val[i]) ss += __expf(zs[i][j] - mm);
        m[j] = mm; sv[j] = ss;
    }
    #pragma unroll
    for (int off = 8; off > 0; off >>= 1) {
        #pragma unroll
        for (int j = 0; j < 4; j++) {
            float mo = __shfl_down_sync(0xffffffffu, m[j],  off, 16);
            float so = __shfl_down_sync(0xffffffffu, sv[j], off, 16);
            float M2 = fmaxf(m[j], mo);
            sv[j] = sv[j] * __expf(m[j] - M2) + so * __expf(mo - M2);
            m[j] = M2;
        }
    }
    if (eg == 0) {
        #pragma unroll
        for (int j = 0; j < 4; j++) {
            g_partM[(c0 + j) * MAXNB + blockIdx.x] = m[j];
            g_partS[(c0 + j) * MAXNB + blockIdx.x] = sv[j];
        }
    }
}

__global__ void k_combine(int NB)
{
    int c = blockIdx.x, t = threadIdx.x;
    float m = -1e30f, s = 0.f;
    for (int b = t; b < NB; b += 256) {
        float mb = g_partM[c * MAXNB + b], sb = g_partS[c * MAXNB + b];
        float M2 = fmaxf(m, mb);
        s = s * __expf(m - M2) + sb * __expf(mb - M2);
        m = M2;
    }
    __shared__ float sm[256], ss[256];
    sm[t] = m; ss[t] = s; __syncthreads();
    for (int off = 128; off > 0; off >>= 1) {
        if (t < off) {
            float M2 = fmaxf(sm[t], sm[t + off]);
            ss[t] = ss[t] * __expf(sm[t] - M2) + ss[t + off] * __expf(sm[t + off] - M2);
            sm[t] = M2;
        }
        __syncthreads();
    }
    if (t == 0) { g_Mg[c] = sm[0]; g_invS[c] = 1.f / ss[0]; }
}

__global__ void k_pass2(float4* __restrict__ out, int total4)
{
    int i = blockIdx.x * 256 + threadIdx.x;
    if (i >= total4) return;
    int c0 = (i * 4) & 63;
    float4 o = out[i];
    const float4 zz = *(const float4*)&g_zbuf[(size_t)i * 4];
    o.x *= __expf(zz.x - g_Mg[c0 + 0]) * g_invS[c0 + 0];
    o.y *= __expf(zz.y - g_Mg[c0 + 1]) * g_invS[c0 + 1];
    o.z *= __expf(zz.z - g_Mg[c0 + 2]) * g_invS[c0 + 2];
    o.w *= __expf(zz.w - g_Mg[c0 + 3]) * g_invS[c0 + 3];
    out[i] = o;
}

extern "C" void kernel_launch(void* const* d_in, const int* in_sizes, int n_in,
                              void* d_out, int out_size)
{
    const float* eemb = (const float*)d_in[0];
    const float* ne   = (const float*)d_in[2];
    const float* Wa   = (const float*)d_in[3];
    const float* ba   = (const float*)d_in[4];
    const float* Wu   = (const float*)d_in[5];
    const float* bu   = (const float*)d_in[6];
    const float* We   = (const float*)d_in[7];
    const float* be   = (const float*)d_in[8];
    const float* Wn   = (const float*)d_in[9];
    const float* bn   = (const float*)d_in[10];
    const void*  eidx = d_in[11];
    float* out = (float*)d_out;

    int E = in_sizes[0] / 64;
    int N = in_sizes[2] / 64;
    int NB = (E + 63) / 64;

    k_prep<<<1, 256>>>(Wa, ba, Wu, bu, We, be, Wn, bn, (const unsigned*)eidx);
    k_node<<<(N + 31) / 32, 256>>>(ne, N);
    k_edge<<<NB, 256>>>(eemb, eidx, bu, out, E);
    k_combine<<<64, 256>>>(NB);
    int total4 = E * 16;
    k_pass2<<<(total4 + 255) / 256, 256>>>((float4*)out, total4);
}